// round 13
// baseline (speedup 1.0000x reference)
#include <cuda_runtime.h>

// ---------------------------------------------------------------------------
// M1_17008070492428: batched tiny Hopfield attention + classifier head.
//   B=131072 samples, each (S=14, D=16) -> (7,) softmax probs.
// R13 = R12 (75.8us) with __launch_bounds__(128, 5): force regs<=102 so a
//   5th block fits per SM (16 -> 20 resident warps). R12 is issue-bound at
//   67% with no pipe above 30%; +25% warps should convert directly into
//   issue throughput if ptxas's spill cost stays small.
// Pipeline: cp.async double-buffered input staging (stride 20); register-
// resident tf32 MMA QKV + S=QK^T (PI-permuted weights); softmax without
// max-shift; r = wm/Z-weighted column sums of P and t = r@V via shuffle
// reductions on fragments; M stored PI-permuted for the final dot.
// ---------------------------------------------------------------------------

typedef unsigned int u32;
#define LN_EPS 1e-5f
#define FULLM 0xffffffffu

__device__ __forceinline__ u32 f2t(float x) {          // f32 bits as tf32
    return __float_as_uint(x);
}
__device__ __forceinline__ void cpasync16(void* smem, const void* gmem) {
    u32 s = (u32)__cvta_generic_to_shared(smem);
    asm volatile("cp.async.ca.shared.global [%0], [%1], 16;" :: "r"(s), "l"(gmem));
}
__device__ __forceinline__ void cp_commit() {
    asm volatile("cp.async.commit_group;");
}
__device__ __forceinline__ void cp_wait1() {
    asm volatile("cp.async.wait_group 1;");
}
__device__ __forceinline__ void mma8(float& d0, float& d1, float& d2, float& d3,
                                     u32 a0, u32 a1, u32 a2, u32 a3,
                                     u32 b0, u32 b1,
                                     float c0, float c1, float c2, float c3) {
    asm("mma.sync.aligned.m16n8k8.row.col.f32.tf32.tf32.f32 "
        "{%0,%1,%2,%3},{%4,%5,%6,%7},{%8,%9},{%10,%11,%12,%13};"
        : "=f"(d0), "=f"(d1), "=f"(d2), "=f"(d3)
        : "r"(a0), "r"(a1), "r"(a2), "r"(a3), "r"(b0), "r"(b1),
          "f"(c0), "f"(c1), "f"(c2), "f"(c3));
}

struct __align__(16) Params {
    float wq[16][16], wk[16][16], wv[16][16];  // PI-permuted rows, LN-gamma folded
    float bq[16], bk[16], bv[16];              // PI-permuted, LN-beta folded
    float M[7][16];                            // (Wb@Wo) with PI-permuted columns
    float ez[8];
    float wm[16];                              // Wm padded with zeros
};
__device__ Params g_P;

__global__ void setup_kernel(
    const float* __restrict__ lnqg, const float* __restrict__ lnqb,
    const float* __restrict__ lnkg, const float* __restrict__ lnkb,
    const float* __restrict__ lnvg, const float* __restrict__ lnvb,
    const float* __restrict__ Wq,  const float* __restrict__ bq,
    const float* __restrict__ Wk,  const float* __restrict__ bk,
    const float* __restrict__ Wv,  const float* __restrict__ bv,
    const float* __restrict__ Wo,  const float* __restrict__ bo,
    const float* __restrict__ Wm,  const float* __restrict__ bm,
    const float* __restrict__ Wb,  const float* __restrict__ bb)
{
    const int PI[16] = {0,4,1,5,2,6,3,7, 8,12,9,13,10,14,11,15};
    const int t = threadIdx.x;           // 256 threads, 1 block
    const int e = t >> 4, d = t & 15;
    const int pe = PI[e];
    g_P.wq[e][d] = Wq[pe * 16 + d] * lnqg[d];
    g_P.wk[e][d] = Wk[pe * 16 + d] * lnkg[d];
    g_P.wv[e][d] = Wv[pe * 16 + d] * lnvg[d];
    if (t < 16) {
        const int p = PI[t];
        float aq = bq[p], ak = bk[p], av = bv[p];
        #pragma unroll
        for (int i = 0; i < 16; i++) {
            aq = fmaf(lnqb[i], Wq[p * 16 + i], aq);
            ak = fmaf(lnkb[i], Wk[p * 16 + i], ak);
            av = fmaf(lnvb[i], Wv[p * 16 + i], av);
        }
        g_P.bq[t] = aq; g_P.bk[t] = ak; g_P.bv[t] = av;
        g_P.wm[t] = (t < 14) ? Wm[t] : 0.f;
    }
    if (t < 112) {
        const int c = t >> 4, dd = t & 15;
        const int pd = PI[dd];               // PI-permuted M columns
        float s = 0.f;
        for (int o = 0; o < 128; o++)
            s = fmaf(Wb[c * 128 + o], Wo[o * 16 + pd], s);
        g_P.M[c][dd] = s;
    }
    if (t >= 112 && t < 119) {
        const int c = t - 112;
        float c0 = 0.f;
        for (int s = 0; s < 14; s++) c0 += Wm[s];
        float z = bb[c];
        const float bmv = bm[0];
        for (int o = 0; o < 128; o++)
            z = fmaf(Wb[c * 128 + o], fmaf(c0, bo[o], bmv), z);
        g_P.ez[c] = z;
    }
    if (t == 119) g_P.ez[7] = 0.f;
}

__global__ __launch_bounds__(128, 5) void hopfield_kernel(
    const float* __restrict__ x, float* __restrict__ out, int nB)
{
    // [warp][buffer][sample][16 rows x 20 floats]  = 20 KB
    __shared__ __align__(16) float smT[4][2][2][16 * 20];
    const int tid  = threadIdx.x;
    const int lane = tid & 31;
    const int wid  = tid >> 5;
    const int fg   = lane >> 2;     // 0..7  (row group / B n-col)
    const int tg   = lane & 3;      // 0..3  (thread-in-quad)

    // ---- persistent weight B-fragments (raw f32 = truncated tf32) ----
    u32   bw[3][2][2][2];           // [proj][ntile][kstep][reg]
    float bs[3][2][2];
    {
        const float* Wp[3] = { &g_P.wq[0][0], &g_P.wk[0][0], &g_P.wv[0][0] };
        const float* Bp[3] = { g_P.bq, g_P.bk, g_P.bv };
        #pragma unroll
        for (int p = 0; p < 3; p++) {
            #pragma unroll
            for (int nt = 0; nt < 2; nt++) {
                #pragma unroll
                for (int ks = 0; ks < 2; ks++) {
                    const float* base = Wp[p] + (fg + 8 * nt) * 16 + 8 * ks;
                    bw[p][nt][ks][0] = f2t(__ldg(base + tg));
                    bw[p][nt][ks][1] = f2t(__ldg(base + tg + 4));
                }
                bs[p][nt][0] = __ldg(Bp[p] + 2 * tg + 8 * nt);
                bs[p][nt][1] = __ldg(Bp[p] + 2 * tg + 8 * nt + 1);
            }
        }
    }
    const float wmLo = g_P.wm[fg];
    const float wmHi = g_P.wm[fg + 8];      // 0 for rows 14,15
    float4 mz = make_float4(0.f, 0.f, 0.f, 0.f);
    float ezv = 0.f;
    if (fg < 7) {
        float2 a = *(const float2*)&g_P.M[fg][2 * tg];      // PI cols: pair with td
        float2 b = *(const float2*)&g_P.M[fg][8 + 2 * tg];
        mz = make_float4(a.x, a.y, b.x, b.y);
        ezv = g_P.ez[fg];
    }
    const int rsel = fg >> 1;        // realign shuffle source lane
    const bool rodd = (fg & 1);

    const int stride = gridDim.x * 4 * 2;

    // prefetch lambda: stream 2 samples at s0p into buffer b (always commits)
    auto prefetch = [&](int s0p, int b) {
        const float4* gp = (const float4*)(x + (long long)s0p * 224);
        #pragma unroll
        for (int j = 0; j < 4; j++) {
            const int i = lane + 32 * j;              // 0..127, need 0..111
            if (i < 112) {
                const int sm2 = (i >= 56);
                const int ii  = i - 56 * sm2;         // float4 idx within sample
                cpasync16(&smT[wid][b][sm2][(ii >> 2) * 20 + ((ii & 3) << 2)],
                          gp + i);
            }
        }
        cp_commit();
    };

    int s0 = (blockIdx.x * 4 + wid) * 2;
    if (s0 >= nB) return;
    prefetch(s0, 0);
    int buf = 0;

    for (; s0 < nB; s0 += stride) {
        const int nxt = s0 + stride;
        prefetch(nxt < nB ? nxt : 0, buf ^ 1);   // clamped: always commit
        cp_wait1();
        __syncwarp();

        #pragma unroll
        for (int smp = 0; smp < 2; smp++) {
            const int samp = s0 + smp;
            const float* Tile = smT[wid][buf][smp];

            // ---- gather x in fragment layout (bank-perfect LDS.32) ----
            float xlo[4], xhi[4];
            #pragma unroll
            for (int u = 0; u < 4; u++) {
                xlo[u] = Tile[fg * 20 + tg + 4 * u];
                xhi[u] = (fg < 6) ? Tile[(fg + 8) * 20 + tg + 4 * u] : 0.f;
            }
            // ---- LN via quad shuffles ----
            float s1l = ((xlo[0] + xlo[1]) + (xlo[2] + xlo[3]));
            float s2l = xlo[0] * xlo[0];
            s2l = fmaf(xlo[1], xlo[1], s2l); s2l = fmaf(xlo[2], xlo[2], s2l); s2l = fmaf(xlo[3], xlo[3], s2l);
            float s1h = ((xhi[0] + xhi[1]) + (xhi[2] + xhi[3]));
            float s2h = xhi[0] * xhi[0];
            s2h = fmaf(xhi[1], xhi[1], s2h); s2h = fmaf(xhi[2], xhi[2], s2h); s2h = fmaf(xhi[3], xhi[3], s2h);
            s1l += __shfl_xor_sync(FULLM, s1l, 1); s1l += __shfl_xor_sync(FULLM, s1l, 2);
            s2l += __shfl_xor_sync(FULLM, s2l, 1); s2l += __shfl_xor_sync(FULLM, s2l, 2);
            s1h += __shfl_xor_sync(FULLM, s1h, 1); s1h += __shfl_xor_sync(FULLM, s1h, 2);
            s2h += __shfl_xor_sync(FULLM, s2h, 1); s2h += __shfl_xor_sync(FULLM, s2h, 2);
            const float mL = s1l * 0.0625f;
            const float rL = rsqrtf(fmaf(-mL, mL, s2l * 0.0625f) + LN_EPS);
            const float mH = s1h * 0.0625f;
            const float rH = rsqrtf(fmaf(-mH, mH, s2h * 0.0625f) + LN_EPS);
            u32 a0 = f2t((xlo[0] - mL) * rL), a1 = f2t((xhi[0] - mH) * rH);
            u32 a2 = f2t((xlo[1] - mL) * rL), a3 = f2t((xhi[1] - mH) * rH);
            u32 a4 = f2t((xlo[2] - mL) * rL), a5 = f2t((xhi[2] - mH) * rH);
            u32 a6 = f2t((xlo[3] - mL) * rL), a7 = f2t((xhi[3] - mH) * rH);

            // ---- QKV (PI-permuted cols): D[:,e] = proj_true[:, PI[e]] ----
            float Q[8], K[8], V[8];
            #pragma unroll
            for (int p = 0; p < 3; p++) {
                float* D = (p == 0) ? Q : ((p == 1) ? K : V);
                #pragma unroll
                for (int nt = 0; nt < 2; nt++) {
                    float d0, d1, d2, d3;
                    mma8(d0, d1, d2, d3, a0, a1, a2, a3,
                         bw[p][nt][0][0], bw[p][nt][0][1],
                         bs[p][nt][0], bs[p][nt][1], bs[p][nt][0], bs[p][nt][1]);
                    mma8(d0, d1, d2, d3, a4, a5, a6, a7,
                         bw[p][nt][1][0], bw[p][nt][1][1], d0, d1, d2, d3);
                    D[nt * 4 + 0] = d0; D[nt * 4 + 1] = d1;
                    D[nt * 4 + 2] = d2; D[nt * 4 + 3] = d3;
                }
            }

            // ---- S = Q K^T : pure register MMA (cols = true keys) ----
            u32 qa0 = f2t(Q[0]), qa1 = f2t(Q[2]), qa2 = f2t(Q[1]), qa3 = f2t(Q[3]);
            u32 qa4 = f2t(Q[4]), qa5 = f2t(Q[6]), qa6 = f2t(Q[5]), qa7 = f2t(Q[7]);
            float t0, t1, t2, t3, u0, u1, u2, u3;
            mma8(t0, t1, t2, t3, qa0, qa1, qa2, qa3, f2t(K[0]), f2t(K[1]), 0.f, 0.f, 0.f, 0.f);
            mma8(t0, t1, t2, t3, qa4, qa5, qa6, qa7, f2t(K[4]), f2t(K[5]), t0, t1, t2, t3);
            mma8(u0, u1, u2, u3, qa0, qa1, qa2, qa3, f2t(K[2]), f2t(K[3]), 0.f, 0.f, 0.f, 0.f);
            mma8(u0, u1, u2, u3, qa4, qa5, qa6, qa7, f2t(K[6]), f2t(K[7]), u0, u1, u2, u3);
            if (tg == 3) { u0 = -1e30f; u1 = -1e30f; u2 = -1e30f; u3 = -1e30f; }  // keys 14,15

            // ---- softmax rows WITHOUT max-shift (scores are O(1)) ----
            float e0 = __expf(t0), e1 = __expf(t1), e4 = __expf(u0), e5 = __expf(u1);
            float e2 = __expf(t2), e3 = __expf(t3), e6 = __expf(u2), e7 = __expf(u3);
            float sl = (e0 + e1) + (e4 + e5);
            sl += __shfl_xor_sync(FULLM, sl, 1); sl += __shfl_xor_sync(FULLM, sl, 2);
            float sh = (e2 + e3) + (e6 + e7);
            sh += __shfl_xor_sync(FULLM, sh, 1); sh += __shfl_xor_sync(FULLM, sh, 2);
            const float wl = wmLo * __fdividef(1.f, sl);
            const float wh = wmHi * __fdividef(1.f, sh);

            // ---- r[key] = sum_q wP[q][key]  (reduce over fg) ----
            float rA = fmaf(e0, wl, e2 * wh);        // key = 2tg
            float rB = fmaf(e1, wl, e3 * wh);        // key = 2tg+1
            float rC = fmaf(e4, wl, e6 * wh);        // key = 8+2tg
            float rD = fmaf(e5, wl, e7 * wh);        // key = 8+2tg+1
            #pragma unroll
            for (int off = 4; off <= 16; off <<= 1) {
                rA += __shfl_xor_sync(FULLM, rA, off);
                rB += __shfl_xor_sync(FULLM, rB, off);
                rC += __shfl_xor_sync(FULLM, rC, off);
                rD += __shfl_xor_sync(FULLM, rD, off);
            }
            // realign: r_lo = r[fg], r_hi = r[fg+8]
            const float rAs = __shfl_sync(FULLM, rA, rsel);
            const float rBs = __shfl_sync(FULLM, rB, rsel);
            const float rCs = __shfl_sync(FULLM, rC, rsel);
            const float rDs = __shfl_sync(FULLM, rD, rsel);
            const float r_lo = rodd ? rBs : rAs;
            const float r_hi = rodd ? rDs : rCs;

            // ---- t over PI-cols: td0..td3 = t[PI[2tg]], t[PI[2tg+1]], ... ----
            float td0 = fmaf(r_lo, V[0], r_hi * V[2]);
            float td1 = fmaf(r_lo, V[1], r_hi * V[3]);
            float td2 = fmaf(r_lo, V[4], r_hi * V[6]);
            float td3 = fmaf(r_lo, V[5], r_hi * V[7]);
            #pragma unroll
            for (int off = 4; off <= 16; off <<= 1) {
                td0 += __shfl_xor_sync(FULLM, td0, off);
                td1 += __shfl_xor_sync(FULLM, td1, off);
                td2 += __shfl_xor_sync(FULLM, td2, off);
                td3 += __shfl_xor_sync(FULLM, td3, off);
            }

            // ---- z[c]: M stored PI-permuted, so mz pairs with td exactly ----
            float z = (fg < 7)
                ? fmaf(mz.x, td0, fmaf(mz.y, td1, fmaf(mz.z, td2, mz.w * td3)))
                : 0.f;
            z += __shfl_xor_sync(FULLM, z, 1);
            z += __shfl_xor_sync(FULLM, z, 2);
            // 7-class softmax without max-shift: |z| is O(1), no overflow risk
            float ex = (fg < 7) ? __expf(z + ezv) : 0.f;
            float se = ex;
            se += __shfl_xor_sync(FULLM, se, 4);
            se += __shfl_xor_sync(FULLM, se, 8);
            se += __shfl_xor_sync(FULLM, se, 16);
            if (tg == 0 && fg < 7)
                out[samp * 7 + fg] = __fdividef(ex, se);
        }
        buf ^= 1;
    }
}

extern "C" void kernel_launch(void* const* d_in, const int* in_sizes, int n_in,
                              void* d_out, int out_size)
{
    const float* sample = (const float*)d_in[0];
    setup_kernel<<<1, 256>>>(
        (const float*)d_in[1],  (const float*)d_in[2],
        (const float*)d_in[3],  (const float*)d_in[4],
        (const float*)d_in[5],  (const float*)d_in[6],
        (const float*)d_in[7],  (const float*)d_in[8],
        (const float*)d_in[9],  (const float*)d_in[10],
        (const float*)d_in[11], (const float*)d_in[12],
        (const float*)d_in[13], (const float*)d_in[14],
        (const float*)d_in[15], (const float*)d_in[16],
        (const float*)d_in[17], (const float*)d_in[18]);

    const int nB = in_sizes[0] / 224;   // B = 131072
    hopfield_kernel<<<2048, 128>>>(sample, (float*)d_out, nB);
}

// round 14
// speedup vs baseline: 1.0496x; 1.0496x over previous
#include <cuda_runtime.h>

// ---------------------------------------------------------------------------
// M1_17008070492428: batched tiny Hopfield attention + classifier head.
//   B=131072 samples, each (S=14, D=16) -> (7,) softmax probs.
// R14 = R12 (75.8us) with the classifier matrix folded into the V path:
//   z[c] = sum_k r[k] * G[k][c] + ez[c],  G = xhat @ (M@Wv_eff)^T + M@bv_eff
//   (project straight into 7-class space). Deletes V's 2nd MMA n-tile,
//   the 12-shfl td reduction, the z quad-dot and 2 shfl, 1 shfl in se.
//   launch_bounds stays (128,4) - occupancy pushes regressed twice.
// Pipeline: cp.async double-buffered input staging (stride 20); register-
// resident tf32 MMA QKV/S (PI-permuted Q,K weights); softmax without
// max-shift; r = wm/Z-weighted column sums of P via shuffle reductions.
// ---------------------------------------------------------------------------

typedef unsigned int u32;
#define LN_EPS 1e-5f
#define FULLM 0xffffffffu

__device__ __forceinline__ u32 f2t(float x) {          // f32 bits as tf32
    return __float_as_uint(x);
}
__device__ __forceinline__ void cpasync16(void* smem, const void* gmem) {
    u32 s = (u32)__cvta_generic_to_shared(smem);
    asm volatile("cp.async.ca.shared.global [%0], [%1], 16;" :: "r"(s), "l"(gmem));
}
__device__ __forceinline__ void cp_commit() {
    asm volatile("cp.async.commit_group;");
}
__device__ __forceinline__ void cp_wait1() {
    asm volatile("cp.async.wait_group 1;");
}
__device__ __forceinline__ void mma8(float& d0, float& d1, float& d2, float& d3,
                                     u32 a0, u32 a1, u32 a2, u32 a3,
                                     u32 b0, u32 b1,
                                     float c0, float c1, float c2, float c3) {
    asm("mma.sync.aligned.m16n8k8.row.col.f32.tf32.tf32.f32 "
        "{%0,%1,%2,%3},{%4,%5,%6,%7},{%8,%9},{%10,%11,%12,%13};"
        : "=f"(d0), "=f"(d1), "=f"(d2), "=f"(d3)
        : "r"(a0), "r"(a1), "r"(a2), "r"(a3), "r"(b0), "r"(b1),
          "f"(c0), "f"(c1), "f"(c2), "f"(c3));
}

struct __align__(16) Params {
    float wq[16][16], wk[16][16];   // PI-permuted rows, LN-gamma folded
    float bq[16], bk[16];           // PI-permuted, LN-beta folded
    float wg[8][16];                // M @ Wv_eff (true dims, row 7 = 0)
    float bg[8];                    // M @ bv_eff (bg[7] = 0)
    float M[7][16];                 // Wb @ Wo (true cols; setup scratch)
    float ez[8];
    float wm[16];                   // Wm padded with zeros
};
__device__ Params g_P;

__global__ void setup_kernel(
    const float* __restrict__ lnqg, const float* __restrict__ lnqb,
    const float* __restrict__ lnkg, const float* __restrict__ lnkb,
    const float* __restrict__ lnvg, const float* __restrict__ lnvb,
    const float* __restrict__ Wq,  const float* __restrict__ bq,
    const float* __restrict__ Wk,  const float* __restrict__ bk,
    const float* __restrict__ Wv,  const float* __restrict__ bv,
    const float* __restrict__ Wo,  const float* __restrict__ bo,
    const float* __restrict__ Wm,  const float* __restrict__ bm,
    const float* __restrict__ Wb,  const float* __restrict__ bb)
{
    const int PI[16] = {0,4,1,5,2,6,3,7, 8,12,9,13,10,14,11,15};
    const int t = threadIdx.x;           // 256 threads, 1 block
    const int e = t >> 4, d = t & 15;
    const int pe = PI[e];
    g_P.wq[e][d] = Wq[pe * 16 + d] * lnqg[d];
    g_P.wk[e][d] = Wk[pe * 16 + d] * lnkg[d];
    if (t < 16) {
        const int p = PI[t];
        float aq = bq[p], ak = bk[p];
        #pragma unroll
        for (int i = 0; i < 16; i++) {
            aq = fmaf(lnqb[i], Wq[p * 16 + i], aq);
            ak = fmaf(lnkb[i], Wk[p * 16 + i], ak);
        }
        g_P.bq[t] = aq; g_P.bk[t] = ak;
        g_P.wm[t] = (t < 14) ? Wm[t] : 0.f;
    }
    if (t < 112) {                       // M_true[c][d] = (Wb @ Wo)[c][d]
        const int c = t >> 4, dd = t & 15;
        float s = 0.f;
        for (int o = 0; o < 128; o++)
            s = fmaf(Wb[c * 128 + o], Wo[o * 16 + dd], s);
        g_P.M[c][dd] = s;
    }
    if (t >= 112 && t < 119) {
        const int c = t - 112;
        float c0 = 0.f;
        for (int s = 0; s < 14; s++) c0 += Wm[s];
        float z = bb[c];
        const float bmv = bm[0];
        for (int o = 0; o < 128; o++)
            z = fmaf(Wb[c * 128 + o], fmaf(c0, bo[o], bmv), z);
        g_P.ez[c] = z;
    }
    if (t == 119) g_P.ez[7] = 0.f;
    __syncthreads();

    // phase 2: fold M into the V projection
    if (t < 128) {                       // wg[c][i] = sum_d M[c][d] Wv[d][i] * g_v[i]
        const int c = t >> 4, i = t & 15;
        float s = 0.f;
        if (c < 7)
            for (int dd = 0; dd < 16; dd++)
                s = fmaf(g_P.M[c][dd], Wv[dd * 16 + i], s);
        g_P.wg[c][i] = s * lnvg[i];
    }
    if (t >= 128 && t < 136) {           // bg[c] = sum_d M[c][d] bv_eff[d]
        const int c = t - 128;
        float s = 0.f;
        if (c < 7) {
            for (int dd = 0; dd < 16; dd++) {
                float bveff = bv[dd];
                for (int i = 0; i < 16; i++)
                    bveff = fmaf(lnvb[i], Wv[dd * 16 + i], bveff);
                s = fmaf(g_P.M[c][dd], bveff, s);
            }
        }
        g_P.bg[c] = s;
    }
}

__global__ __launch_bounds__(128, 4) void hopfield_kernel(
    const float* __restrict__ x, float* __restrict__ out, int nB)
{
    // [warp][buffer][sample][16 rows x 20 floats]  = 20 KB
    __shared__ __align__(16) float smT[4][2][2][16 * 20];
    const int tid  = threadIdx.x;
    const int lane = tid & 31;
    const int wid  = tid >> 5;
    const int fg   = lane >> 2;     // 0..7  (row group / B n-col)
    const int tg   = lane & 3;      // 0..3  (thread-in-quad)

    // ---- persistent weight B-fragments (raw f32 = truncated tf32) ----
    u32   bw[2][2][2][2];           // [Q/K][ntile][kstep][reg]
    float bs[2][2][2];
    {
        const float* Wp[2] = { &g_P.wq[0][0], &g_P.wk[0][0] };
        const float* Bp[2] = { g_P.bq, g_P.bk };
        #pragma unroll
        for (int p = 0; p < 2; p++) {
            #pragma unroll
            for (int nt = 0; nt < 2; nt++) {
                #pragma unroll
                for (int ks = 0; ks < 2; ks++) {
                    const float* base = Wp[p] + (fg + 8 * nt) * 16 + 8 * ks;
                    bw[p][nt][ks][0] = f2t(__ldg(base + tg));
                    bw[p][nt][ks][1] = f2t(__ldg(base + tg + 4));
                }
                bs[p][nt][0] = __ldg(Bp[p] + 2 * tg + 8 * nt);
                bs[p][nt][1] = __ldg(Bp[p] + 2 * tg + 8 * nt + 1);
            }
        }
    }
    u32 bwg[2][2];                  // G projection (single n-tile)
    #pragma unroll
    for (int ks = 0; ks < 2; ks++) {
        bwg[ks][0] = f2t(__ldg(&g_P.wg[fg][8 * ks + tg]));
        bwg[ks][1] = f2t(__ldg(&g_P.wg[fg][8 * ks + tg + 4]));
    }
    const float bg0 = g_P.bg[2 * tg], bg1 = g_P.bg[2 * tg + 1];
    const float ezA = g_P.ez[2 * tg], ezB = g_P.ez[2 * tg + 1];
    const float wmLo = g_P.wm[fg];
    const float wmHi = g_P.wm[fg + 8];      // 0 for rows 14,15
    const int rsel = fg >> 1;        // realign shuffle source lane
    const bool rodd = (fg & 1);

    const int stride = gridDim.x * 4 * 2;

    // prefetch lambda: stream 2 samples at s0p into buffer b (always commits)
    auto prefetch = [&](int s0p, int b) {
        const float4* gp = (const float4*)(x + (long long)s0p * 224);
        #pragma unroll
        for (int j = 0; j < 4; j++) {
            const int i = lane + 32 * j;              // 0..127, need 0..111
            if (i < 112) {
                const int sm2 = (i >= 56);
                const int ii  = i - 56 * sm2;         // float4 idx within sample
                cpasync16(&smT[wid][b][sm2][(ii >> 2) * 20 + ((ii & 3) << 2)],
                          gp + i);
            }
        }
        cp_commit();
    };

    int s0 = (blockIdx.x * 4 + wid) * 2;
    if (s0 >= nB) return;
    prefetch(s0, 0);
    int buf = 0;

    for (; s0 < nB; s0 += stride) {
        const int nxt = s0 + stride;
        prefetch(nxt < nB ? nxt : 0, buf ^ 1);   // clamped: always commit
        cp_wait1();
        __syncwarp();

        #pragma unroll
        for (int smp = 0; smp < 2; smp++) {
            const int samp = s0 + smp;
            const float* Tile = smT[wid][buf][smp];

            // ---- gather x in fragment layout (bank-perfect LDS.32) ----
            float xlo[4], xhi[4];
            #pragma unroll
            for (int u = 0; u < 4; u++) {
                xlo[u] = Tile[fg * 20 + tg + 4 * u];
                xhi[u] = (fg < 6) ? Tile[(fg + 8) * 20 + tg + 4 * u] : 0.f;
            }
            // ---- LN via quad shuffles ----
            float s1l = ((xlo[0] + xlo[1]) + (xlo[2] + xlo[3]));
            float s2l = xlo[0] * xlo[0];
            s2l = fmaf(xlo[1], xlo[1], s2l); s2l = fmaf(xlo[2], xlo[2], s2l); s2l = fmaf(xlo[3], xlo[3], s2l);
            float s1h = ((xhi[0] + xhi[1]) + (xhi[2] + xhi[3]));
            float s2h = xhi[0] * xhi[0];
            s2h = fmaf(xhi[1], xhi[1], s2h); s2h = fmaf(xhi[2], xhi[2], s2h); s2h = fmaf(xhi[3], xhi[3], s2h);
            s1l += __shfl_xor_sync(FULLM, s1l, 1); s1l += __shfl_xor_sync(FULLM, s1l, 2);
            s2l += __shfl_xor_sync(FULLM, s2l, 1); s2l += __shfl_xor_sync(FULLM, s2l, 2);
            s1h += __shfl_xor_sync(FULLM, s1h, 1); s1h += __shfl_xor_sync(FULLM, s1h, 2);
            s2h += __shfl_xor_sync(FULLM, s2h, 1); s2h += __shfl_xor_sync(FULLM, s2h, 2);
            const float mL = s1l * 0.0625f;
            const float rL = rsqrtf(fmaf(-mL, mL, s2l * 0.0625f) + LN_EPS);
            const float mH = s1h * 0.0625f;
            const float rH = rsqrtf(fmaf(-mH, mH, s2h * 0.0625f) + LN_EPS);
            u32 a0 = f2t((xlo[0] - mL) * rL), a1 = f2t((xhi[0] - mH) * rH);
            u32 a2 = f2t((xlo[1] - mL) * rL), a3 = f2t((xhi[1] - mH) * rH);
            u32 a4 = f2t((xlo[2] - mL) * rL), a5 = f2t((xhi[2] - mH) * rH);
            u32 a6 = f2t((xlo[3] - mL) * rL), a7 = f2t((xhi[3] - mH) * rH);

            // ---- Q,K (PI-permuted cols) ----
            float Q[8], K[8];
            #pragma unroll
            for (int p = 0; p < 2; p++) {
                float* D = (p == 0) ? Q : K;
                #pragma unroll
                for (int nt = 0; nt < 2; nt++) {
                    float d0, d1, d2, d3;
                    mma8(d0, d1, d2, d3, a0, a1, a2, a3,
                         bw[p][nt][0][0], bw[p][nt][0][1],
                         bs[p][nt][0], bs[p][nt][1], bs[p][nt][0], bs[p][nt][1]);
                    mma8(d0, d1, d2, d3, a4, a5, a6, a7,
                         bw[p][nt][1][0], bw[p][nt][1][1], d0, d1, d2, d3);
                    D[nt * 4 + 0] = d0; D[nt * 4 + 1] = d1;
                    D[nt * 4 + 2] = d2; D[nt * 4 + 3] = d3;
                }
            }
            // ---- G = xhat @ Wg^T + bg : rows = seq pos, cols = class ----
            float g0, g1, g2, g3;
            mma8(g0, g1, g2, g3, a0, a1, a2, a3,
                 bwg[0][0], bwg[0][1], bg0, bg1, bg0, bg1);
            mma8(g0, g1, g2, g3, a4, a5, a6, a7,
                 bwg[1][0], bwg[1][1], g0, g1, g2, g3);

            // ---- S = Q K^T : pure register MMA (cols = true keys) ----
            u32 qa0 = f2t(Q[0]), qa1 = f2t(Q[2]), qa2 = f2t(Q[1]), qa3 = f2t(Q[3]);
            u32 qa4 = f2t(Q[4]), qa5 = f2t(Q[6]), qa6 = f2t(Q[5]), qa7 = f2t(Q[7]);
            float t0, t1, t2, t3, u0, u1, u2, u3;
            mma8(t0, t1, t2, t3, qa0, qa1, qa2, qa3, f2t(K[0]), f2t(K[1]), 0.f, 0.f, 0.f, 0.f);
            mma8(t0, t1, t2, t3, qa4, qa5, qa6, qa7, f2t(K[4]), f2t(K[5]), t0, t1, t2, t3);
            mma8(u0, u1, u2, u3, qa0, qa1, qa2, qa3, f2t(K[2]), f2t(K[3]), 0.f, 0.f, 0.f, 0.f);
            mma8(u0, u1, u2, u3, qa4, qa5, qa6, qa7, f2t(K[6]), f2t(K[7]), u0, u1, u2, u3);
            if (tg == 3) { u0 = -1e30f; u1 = -1e30f; u2 = -1e30f; u3 = -1e30f; }  // keys 14,15

            // ---- softmax rows WITHOUT max-shift (scores are O(1)) ----
            float e0 = __expf(t0), e1 = __expf(t1), e4 = __expf(u0), e5 = __expf(u1);
            float e2 = __expf(t2), e3 = __expf(t3), e6 = __expf(u2), e7 = __expf(u3);
            float sl = (e0 + e1) + (e4 + e5);
            sl += __shfl_xor_sync(FULLM, sl, 1); sl += __shfl_xor_sync(FULLM, sl, 2);
            float sh = (e2 + e3) + (e6 + e7);
            sh += __shfl_xor_sync(FULLM, sh, 1); sh += __shfl_xor_sync(FULLM, sh, 2);
            const float wl = wmLo * __fdividef(1.f, sl);
            const float wh = wmHi * __fdividef(1.f, sh);

            // ---- r[key] = sum_q wP[q][key]  (reduce over fg) ----
            float rA = fmaf(e0, wl, e2 * wh);        // key = 2tg
            float rB = fmaf(e1, wl, e3 * wh);        // key = 2tg+1
            float rC = fmaf(e4, wl, e6 * wh);        // key = 8+2tg
            float rD = fmaf(e5, wl, e7 * wh);        // key = 8+2tg+1
            #pragma unroll
            for (int off = 4; off <= 16; off <<= 1) {
                rA += __shfl_xor_sync(FULLM, rA, off);
                rB += __shfl_xor_sync(FULLM, rB, off);
                rC += __shfl_xor_sync(FULLM, rC, off);
                rD += __shfl_xor_sync(FULLM, rD, off);
            }
            // realign: r_lo = r[fg], r_hi = r[fg+8]
            const float rAs = __shfl_sync(FULLM, rA, rsel);
            const float rBs = __shfl_sync(FULLM, rB, rsel);
            const float rCs = __shfl_sync(FULLM, rC, rsel);
            const float rDs = __shfl_sync(FULLM, rD, rsel);
            const float r_lo = rodd ? rBs : rAs;
            const float r_hi = rodd ? rDs : rCs;

            // ---- z[c] = sum_k r[k] G[k][c]  (reduce over fg) ----
            float zA = fmaf(r_lo, g0, r_hi * g2);    // class 2tg
            float zB = fmaf(r_lo, g1, r_hi * g3);    // class 2tg+1
            #pragma unroll
            for (int off = 4; off <= 16; off <<= 1) {
                zA += __shfl_xor_sync(FULLM, zA, off);
                zB += __shfl_xor_sync(FULLM, zB, off);
            }

            // ---- 7-class softmax (no max-shift; class 7 masked) ----
            float exA = __expf(zA + ezA);
            float exB = (tg == 3) ? 0.f : __expf(zB + ezB);
            float se = exA + exB;
            se += __shfl_xor_sync(FULLM, se, 1);
            se += __shfl_xor_sync(FULLM, se, 2);
            if (fg == 0) {
                const float inv = __fdividef(1.f, se);
                out[samp * 7 + 2 * tg] = exA * inv;
                if (tg < 3) out[samp * 7 + 2 * tg + 1] = exB * inv;
            }
        }
        buf ^= 1;
    }
}

extern "C" void kernel_launch(void* const* d_in, const int* in_sizes, int n_in,
                              void* d_out, int out_size)
{
    const float* sample = (const float*)d_in[0];
    setup_kernel<<<1, 256>>>(
        (const float*)d_in[1],  (const float*)d_in[2],
        (const float*)d_in[3],  (const float*)d_in[4],
        (const float*)d_in[5],  (const float*)d_in[6],
        (const float*)d_in[7],  (const float*)d_in[8],
        (const float*)d_in[9],  (const float*)d_in[10],
        (const float*)d_in[11], (const float*)d_in[12],
        (const float*)d_in[13], (const float*)d_in[14],
        (const float*)d_in[15], (const float*)d_in[16],
        (const float*)d_in[17], (const float*)d_in[18]);

    const int nB = in_sizes[0] / 224;   // B = 131072
    hopfield_kernel<<<2048, 128>>>(sample, (float*)d_out, nB);
}

// round 15
// speedup vs baseline: 1.1389x; 1.0851x over previous
#include <cuda_runtime.h>

// ---------------------------------------------------------------------------
// M1_17008070492428: batched tiny Hopfield attention + classifier head.
//   B=131072 samples, each (S=14, D=16) -> (7,) softmax probs.
// R15 = R12 (best, 75.8us) + k-dim permutation SIGMA on the QKV MMAs:
//   SIGMA(c) = 4*(c%4) + c/4 applied to BOTH x-fragment and weight columns
//   (contraction invariant). Thread (fg,tg)'s A-regs become the contiguous
//   x[fg][4tg..4tg+3], so the smem stage stays plain row-major (direct
//   cp.async 16B writes) and the gather is 2 LDS.128 instead of 8 LDS.32
//   + index math. Weights absorb SIGMA at (loop-invariant) frag preload.
//   R14 lesson applied: removes overhead without removing overlappable work.
// Pipeline: cp.async double-buffered staging; register-resident tf32 MMA
// QKV + S=QK^T (PI-permuted e-dim); softmax without max-shift; r/td/z via
// shuffle reductions on fragments; M stored PI-permuted.
// ---------------------------------------------------------------------------

typedef unsigned int u32;
#define LN_EPS 1e-5f
#define FULLM 0xffffffffu

__device__ __forceinline__ u32 f2t(float x) {          // f32 bits as tf32
    return __float_as_uint(x);
}
__device__ __forceinline__ void cpasync16(void* smem, const void* gmem) {
    u32 s = (u32)__cvta_generic_to_shared(smem);
    asm volatile("cp.async.ca.shared.global [%0], [%1], 16;" :: "r"(s), "l"(gmem));
}
__device__ __forceinline__ void cp_commit() {
    asm volatile("cp.async.commit_group;");
}
__device__ __forceinline__ void cp_wait1() {
    asm volatile("cp.async.wait_group 1;");
}
__device__ __forceinline__ void mma8(float& d0, float& d1, float& d2, float& d3,
                                     u32 a0, u32 a1, u32 a2, u32 a3,
                                     u32 b0, u32 b1,
                                     float c0, float c1, float c2, float c3) {
    asm("mma.sync.aligned.m16n8k8.row.col.f32.tf32.tf32.f32 "
        "{%0,%1,%2,%3},{%4,%5,%6,%7},{%8,%9},{%10,%11,%12,%13};"
        : "=f"(d0), "=f"(d1), "=f"(d2), "=f"(d3)
        : "r"(a0), "r"(a1), "r"(a2), "r"(a3), "r"(b0), "r"(b1),
          "f"(c0), "f"(c1), "f"(c2), "f"(c3));
}

struct __align__(16) Params {
    float wq[16][16], wk[16][16], wv[16][16];  // PI-permuted rows, LN-gamma folded
    float bq[16], bk[16], bv[16];              // PI-permuted, LN-beta folded
    float M[7][16];                            // (Wb@Wo) with PI-permuted columns
    float ez[8];
    float wm[16];                              // Wm padded with zeros
};
__device__ Params g_P;

__global__ void setup_kernel(
    const float* __restrict__ lnqg, const float* __restrict__ lnqb,
    const float* __restrict__ lnkg, const float* __restrict__ lnkb,
    const float* __restrict__ lnvg, const float* __restrict__ lnvb,
    const float* __restrict__ Wq,  const float* __restrict__ bq,
    const float* __restrict__ Wk,  const float* __restrict__ bk,
    const float* __restrict__ Wv,  const float* __restrict__ bv,
    const float* __restrict__ Wo,  const float* __restrict__ bo,
    const float* __restrict__ Wm,  const float* __restrict__ bm,
    const float* __restrict__ Wb,  const float* __restrict__ bb)
{
    const int PI[16] = {0,4,1,5,2,6,3,7, 8,12,9,13,10,14,11,15};
    const int t = threadIdx.x;           // 256 threads, 1 block
    const int e = t >> 4, d = t & 15;
    const int pe = PI[e];
    g_P.wq[e][d] = Wq[pe * 16 + d] * lnqg[d];
    g_P.wk[e][d] = Wk[pe * 16 + d] * lnkg[d];
    g_P.wv[e][d] = Wv[pe * 16 + d] * lnvg[d];
    if (t < 16) {
        const int p = PI[t];
        float aq = bq[p], ak = bk[p], av = bv[p];
        #pragma unroll
        for (int i = 0; i < 16; i++) {
            aq = fmaf(lnqb[i], Wq[p * 16 + i], aq);
            ak = fmaf(lnkb[i], Wk[p * 16 + i], ak);
            av = fmaf(lnvb[i], Wv[p * 16 + i], av);
        }
        g_P.bq[t] = aq; g_P.bk[t] = ak; g_P.bv[t] = av;
        g_P.wm[t] = (t < 14) ? Wm[t] : 0.f;
    }
    if (t < 112) {
        const int c = t >> 4, dd = t & 15;
        const int pd = PI[dd];               // PI-permuted M columns
        float s = 0.f;
        for (int o = 0; o < 128; o++)
            s = fmaf(Wb[c * 128 + o], Wo[o * 16 + pd], s);
        g_P.M[c][dd] = s;
    }
    if (t >= 112 && t < 119) {
        const int c = t - 112;
        float c0 = 0.f;
        for (int s = 0; s < 14; s++) c0 += Wm[s];
        float z = bb[c];
        const float bmv = bm[0];
        for (int o = 0; o < 128; o++)
            z = fmaf(Wb[c * 128 + o], fmaf(c0, bo[o], bmv), z);
        g_P.ez[c] = z;
    }
    if (t == 119) g_P.ez[7] = 0.f;
}

__global__ __launch_bounds__(128, 4) void hopfield_kernel(
    const float* __restrict__ x, float* __restrict__ out, int nB)
{
    // [warp][buffer][sample][16 rows x 16 floats, row-major]  = 16 KB
    __shared__ __align__(16) float smT[4][2][2][256];
    const int tid  = threadIdx.x;
    const int lane = tid & 31;
    const int wid  = tid >> 5;
    const int fg   = lane >> 2;     // 0..7  (row group / B n-col)
    const int tg   = lane & 3;      // 0..3  (thread-in-quad)

    // ---- persistent weight B-fragments, SIGMA-indexed columns ----
    // bw[p][nt][ks][r] = W[e = fg+8nt][4*tg + 2*ks + r]
    u32   bw[3][2][2][2];
    float bs[3][2][2];
    {
        const float* Wp[3] = { &g_P.wq[0][0], &g_P.wk[0][0], &g_P.wv[0][0] };
        const float* Bp[3] = { g_P.bq, g_P.bk, g_P.bv };
        #pragma unroll
        for (int p = 0; p < 3; p++) {
            #pragma unroll
            for (int nt = 0; nt < 2; nt++) {
                const float* base = Wp[p] + (fg + 8 * nt) * 16 + 4 * tg;
                #pragma unroll
                for (int ks = 0; ks < 2; ks++) {
                    bw[p][nt][ks][0] = f2t(__ldg(base + 2 * ks));
                    bw[p][nt][ks][1] = f2t(__ldg(base + 2 * ks + 1));
                }
                bs[p][nt][0] = __ldg(Bp[p] + 2 * tg + 8 * nt);
                bs[p][nt][1] = __ldg(Bp[p] + 2 * tg + 8 * nt + 1);
            }
        }
    }
    const float wmLo = g_P.wm[fg];
    const float wmHi = g_P.wm[fg + 8];      // 0 for rows 14,15
    float4 mz = make_float4(0.f, 0.f, 0.f, 0.f);
    float ezv = 0.f;
    if (fg < 7) {
        float2 a = *(const float2*)&g_P.M[fg][2 * tg];      // PI cols: pair with td
        float2 b = *(const float2*)&g_P.M[fg][8 + 2 * tg];
        mz = make_float4(a.x, a.y, b.x, b.y);
        ezv = g_P.ez[fg];
    }
    const int rsel = fg >> 1;        // realign shuffle source lane
    const bool rodd = (fg & 1);

    const int stride = gridDim.x * 4 * 2;

    // prefetch: stream 2 samples at s0p into buffer b (row-major, direct)
    auto prefetch = [&](int s0p, int b) {
        const float4* gp = (const float4*)(x + (long long)s0p * 224);
        #pragma unroll
        for (int j = 0; j < 4; j++) {
            const int i = lane + 32 * j;              // 0..127, need 0..111
            if (i < 112) {
                const int sm2 = (i >= 56);
                const int ii  = i - 56 * sm2;         // float4 idx within sample
                cpasync16(&((float4*)smT[wid][b][sm2])[ii], gp + i);
            }
        }
        cp_commit();
    };

    int s0 = (blockIdx.x * 4 + wid) * 2;
    if (s0 >= nB) return;
    prefetch(s0, 0);
    int buf = 0;

    for (; s0 < nB; s0 += stride) {
        const int nxt = s0 + stride;
        prefetch(nxt < nB ? nxt : 0, buf ^ 1);   // clamped: always commit
        cp_wait1();
        __syncwarp();

        #pragma unroll
        for (int smp = 0; smp < 2; smp++) {
            const int samp = s0 + smp;
            const float* Tile = smT[wid][buf][smp];

            // ---- gather x: 2 conflict-free LDS.128 (SIGMA layout) ----
            // xl = x[fg][4tg..4tg+3], xh = x[fg+8][4tg..4tg+3]
            const float4 xl = *(const float4*)&Tile[fg * 16 + 4 * tg];
            const float4 xh = (fg < 6) ? *(const float4*)&Tile[(fg + 8) * 16 + 4 * tg]
                                       : make_float4(0.f, 0.f, 0.f, 0.f);

            // ---- LN via quad shuffles ----
            float s1l = (xl.x + xl.y) + (xl.z + xl.w);
            float s2l = xl.x * xl.x;
            s2l = fmaf(xl.y, xl.y, s2l); s2l = fmaf(xl.z, xl.z, s2l); s2l = fmaf(xl.w, xl.w, s2l);
            float s1h = (xh.x + xh.y) + (xh.z + xh.w);
            float s2h = xh.x * xh.x;
            s2h = fmaf(xh.y, xh.y, s2h); s2h = fmaf(xh.z, xh.z, s2h); s2h = fmaf(xh.w, xh.w, s2h);
            s1l += __shfl_xor_sync(FULLM, s1l, 1); s1l += __shfl_xor_sync(FULLM, s1l, 2);
            s2l += __shfl_xor_sync(FULLM, s2l, 1); s2l += __shfl_xor_sync(FULLM, s2l, 2);
            s1h += __shfl_xor_sync(FULLM, s1h, 1); s1h += __shfl_xor_sync(FULLM, s1h, 2);
            s2h += __shfl_xor_sync(FULLM, s2h, 1); s2h += __shfl_xor_sync(FULLM, s2h, 2);
            const float mL = s1l * 0.0625f;
            const float rL = rsqrtf(fmaf(-mL, mL, s2l * 0.0625f) + LN_EPS);
            const float mH = s1h * 0.0625f;
            const float rH = rsqrtf(fmaf(-mH, mH, s2h * 0.0625f) + LN_EPS);
            // A-regs in SIGMA order: a0/a2 = kstep0, a4/a6 = kstep1
            u32 a0 = f2t((xl.x - mL) * rL), a1 = f2t((xh.x - mH) * rH);
            u32 a2 = f2t((xl.y - mL) * rL), a3 = f2t((xh.y - mH) * rH);
            u32 a4 = f2t((xl.z - mL) * rL), a5 = f2t((xh.z - mH) * rH);
            u32 a6 = f2t((xl.w - mL) * rL), a7 = f2t((xh.w - mH) * rH);

            // ---- QKV (PI-permuted cols; SIGMA-consistent k) ----
            float Q[8], K[8], V[8];
            #pragma unroll
            for (int p = 0; p < 3; p++) {
                float* D = (p == 0) ? Q : ((p == 1) ? K : V);
                #pragma unroll
                for (int nt = 0; nt < 2; nt++) {
                    float d0, d1, d2, d3;
                    mma8(d0, d1, d2, d3, a0, a1, a2, a3,
                         bw[p][nt][0][0], bw[p][nt][0][1],
                         bs[p][nt][0], bs[p][nt][1], bs[p][nt][0], bs[p][nt][1]);
                    mma8(d0, d1, d2, d3, a4, a5, a6, a7,
                         bw[p][nt][1][0], bw[p][nt][1][1], d0, d1, d2, d3);
                    D[nt * 4 + 0] = d0; D[nt * 4 + 1] = d1;
                    D[nt * 4 + 2] = d2; D[nt * 4 + 3] = d3;
                }
            }

            // ---- S = Q K^T : pure register MMA (cols = true keys) ----
            u32 qa0 = f2t(Q[0]), qa1 = f2t(Q[2]), qa2 = f2t(Q[1]), qa3 = f2t(Q[3]);
            u32 qa4 = f2t(Q[4]), qa5 = f2t(Q[6]), qa6 = f2t(Q[5]), qa7 = f2t(Q[7]);
            float t0, t1, t2, t3, u0, u1, u2, u3;
            mma8(t0, t1, t2, t3, qa0, qa1, qa2, qa3, f2t(K[0]), f2t(K[1]), 0.f, 0.f, 0.f, 0.f);
            mma8(t0, t1, t2, t3, qa4, qa5, qa6, qa7, f2t(K[4]), f2t(K[5]), t0, t1, t2, t3);
            mma8(u0, u1, u2, u3, qa0, qa1, qa2, qa3, f2t(K[2]), f2t(K[3]), 0.f, 0.f, 0.f, 0.f);
            mma8(u0, u1, u2, u3, qa4, qa5, qa6, qa7, f2t(K[6]), f2t(K[7]), u0, u1, u2, u3);
            if (tg == 3) { u0 = -1e30f; u1 = -1e30f; u2 = -1e30f; u3 = -1e30f; }  // keys 14,15

            // ---- softmax rows WITHOUT max-shift (scores are O(1)) ----
            float e0 = __expf(t0), e1 = __expf(t1), e4 = __expf(u0), e5 = __expf(u1);
            float e2 = __expf(t2), e3 = __expf(t3), e6 = __expf(u2), e7 = __expf(u3);
            float sl = (e0 + e1) + (e4 + e5);
            sl += __shfl_xor_sync(FULLM, sl, 1); sl += __shfl_xor_sync(FULLM, sl, 2);
            float sh = (e2 + e3) + (e6 + e7);
            sh += __shfl_xor_sync(FULLM, sh, 1); sh += __shfl_xor_sync(FULLM, sh, 2);
            const float wl = wmLo * __fdividef(1.f, sl);
            const float wh = wmHi * __fdividef(1.f, sh);

            // ---- r[key] = sum_q wP[q][key]  (reduce over fg) ----
            float rA = fmaf(e0, wl, e2 * wh);        // key = 2tg
            float rB = fmaf(e1, wl, e3 * wh);        // key = 2tg+1
            float rC = fmaf(e4, wl, e6 * wh);        // key = 8+2tg
            float rD = fmaf(e5, wl, e7 * wh);        // key = 8+2tg+1
            #pragma unroll
            for (int off = 4; off <= 16; off <<= 1) {
                rA += __shfl_xor_sync(FULLM, rA, off);
                rB += __shfl_xor_sync(FULLM, rB, off);
                rC += __shfl_xor_sync(FULLM, rC, off);
                rD += __shfl_xor_sync(FULLM, rD, off);
            }
            // realign: r_lo = r[fg], r_hi = r[fg+8]
            const float rAs = __shfl_sync(FULLM, rA, rsel);
            const float rBs = __shfl_sync(FULLM, rB, rsel);
            const float rCs = __shfl_sync(FULLM, rC, rsel);
            const float rDs = __shfl_sync(FULLM, rD, rsel);
            const float r_lo = rodd ? rBs : rAs;
            const float r_hi = rodd ? rDs : rCs;

            // ---- t over PI-cols: td0..td3 = t[PI[2tg]], t[PI[2tg+1]], ... ----
            float td0 = fmaf(r_lo, V[0], r_hi * V[2]);
            float td1 = fmaf(r_lo, V[1], r_hi * V[3]);
            float td2 = fmaf(r_lo, V[4], r_hi * V[6]);
            float td3 = fmaf(r_lo, V[5], r_hi * V[7]);
            #pragma unroll
            for (int off = 4; off <= 16; off <<= 1) {
                td0 += __shfl_xor_sync(FULLM, td0, off);
                td1 += __shfl_xor_sync(FULLM, td1, off);
                td2 += __shfl_xor_sync(FULLM, td2, off);
                td3 += __shfl_xor_sync(FULLM, td3, off);
            }

            // ---- z[c]: M stored PI-permuted, so mz pairs with td exactly ----
            float z = (fg < 7)
                ? fmaf(mz.x, td0, fmaf(mz.y, td1, fmaf(mz.z, td2, mz.w * td3)))
                : 0.f;
            z += __shfl_xor_sync(FULLM, z, 1);
            z += __shfl_xor_sync(FULLM, z, 2);
            // 7-class softmax without max-shift: |z| is O(1), no overflow risk
            float ex = (fg < 7) ? __expf(z + ezv) : 0.f;
            float se = ex;
            se += __shfl_xor_sync(FULLM, se, 4);
            se += __shfl_xor_sync(FULLM, se, 8);
            se += __shfl_xor_sync(FULLM, se, 16);
            if (tg == 0 && fg < 7)
                out[samp * 7 + fg] = __fdividef(ex, se);
        }
        buf ^= 1;
    }
}

extern "C" void kernel_launch(void* const* d_in, const int* in_sizes, int n_in,
                              void* d_out, int out_size)
{
    const float* sample = (const float*)d_in[0];
    setup_kernel<<<1, 256>>>(
        (const float*)d_in[1],  (const float*)d_in[2],
        (const float*)d_in[3],  (const float*)d_in[4],
        (const float*)d_in[5],  (const float*)d_in[6],
        (const float*)d_in[7],  (const float*)d_in[8],
        (const float*)d_in[9],  (const float*)d_in[10],
        (const float*)d_in[11], (const float*)d_in[12],
        (const float*)d_in[13], (const float*)d_in[14],
        (const float*)d_in[15], (const float*)d_in[16],
        (const float*)d_in[17], (const float*)d_in[18]);

    const int nB = in_sizes[0] / 224;   // B = 131072
    hopfield_kernel<<<2048, 128>>>(sample, (float*)d_out, nB);
}